// round 5
// baseline (speedup 1.0000x reference)
#include <cuda_runtime.h>
#include <cstdint>

// Problem dimensions (fixed by the reference).
#define NW 50000
#define NT 2000
#define ND 50000
#define DO 128
#define DW 256   // word feature dim

// Degree-array layout: one float counter per (relation, dst-node).
constexpr int DEG_WW = 0;
constexpr int DEG_WT = NW;
constexpr int DEG_TT = NW + NT;
constexpr int DEG_WD = NW + 2 * NT;
constexpr int DEG_TD = NW + 2 * NT + ND;
constexpr int NDEG   = NW + 2 * NT + 2 * ND;   // 154000

// ---------------------------------------------------------------------------
// Scratch (static __device__ arrays — allocation-free per harness rules).
// ---------------------------------------------------------------------------
__device__ float g_Wh_ww[(size_t)NW * DO];
__device__ float g_Wh_wd[(size_t)NW * DO];
__device__ float g_Wh_td[(size_t)NT * DO];
__device__ float g_Wh_tt[(size_t)NT * DO];

__device__ float g_s_ww[(size_t)NW * DO];
__device__ float g_s_wt[(size_t)NT * DO];
__device__ float g_s_tt[(size_t)NT * DO];
__device__ float g_s_wd[(size_t)ND * DO];
__device__ float g_s_td[(size_t)ND * DO];

// wt aggregate-first buffers: raw-feature accumulator + edge-weight sums.
__device__ float g_agg_wt[(size_t)NT * DW];
__device__ float g_sumw_wt[NT];

__device__ float g_deg[NDEG];

// rel ids: 0=ww, 2=tt, 3=wd, 4=td (1=wt handled by aggregate-first path)
__device__ __forceinline__ float* wh_ptr(int rel) {
    switch (rel) {
        case 0:  return g_Wh_ww;
        case 2:  return g_Wh_tt;
        case 3:  return g_Wh_wd;
        default: return g_Wh_td;
    }
}
__device__ __forceinline__ float* s_ptr(int rel) {
    switch (rel) {
        case 0:  return g_s_ww;
        case 2:  return g_s_tt;
        case 3:  return g_s_wd;
        default: return g_s_td;
    }
}
__device__ __forceinline__ int deg_off(int rel) {
    switch (rel) {
        case 0:  return DEG_WW;
        case 2:  return DEG_TT;
        case 3:  return DEG_WD;
        default: return DEG_TD;
    }
}

// ---------------------------------------------------------------------------
// Zero accumulators + degrees.
// ---------------------------------------------------------------------------
__global__ void zero_all() {
    size_t i = (size_t)blockIdx.x * blockDim.x + threadIdx.x;
    if (i < (size_t)NW * DO) g_s_ww[i] = 0.0f;
    if (i < (size_t)NT * DO) g_s_tt[i] = 0.0f;
    if (i < (size_t)ND * DO) { g_s_wd[i] = 0.0f; g_s_td[i] = 0.0f; }
    if (i < (size_t)NT * DW) g_agg_wt[i] = 0.0f;
    if (i < (size_t)NT)      g_sumw_wt[i] = 0.0f;
    if (i < (size_t)NDEG)    g_deg[i] = 0.0f;
}

// ---------------------------------------------------------------------------
// Packed-f32x2 GEMM + bias: C[M x 128] = A[M x DIN] @ W[DIN x 128] (+ bias)
// BM=64, BN=128, BK=32, 256 threads, 4x8 microtile (16 f32x2 acc pairs).
// Small register footprint (-> 3 CTAs/SM, 6 warps/SMSP) so the FFMA2 pipe
// stays fed: per k only 3 LDS.128 + splats + 16 FFMA2.
// SCALED_BIAS: C[m] += sumw[m] * bias (aggregate-first epilogue); C is given
// explicitly.
// ---------------------------------------------------------------------------
template <int DIN, bool SCALED_BIAS>
__global__ __launch_bounds__(256, 3)
void gemm_bias_x2(const float* __restrict__ A, const float* __restrict__ W,
                  const float* __restrict__ bias,
                  const float* __restrict__ sumw,
                  float* __restrict__ C, int M) {
    constexpr int BM = 64, BN = 128, BK = 32;
    __shared__ float As[BK][BM];   // transposed: [k][m]
    __shared__ float Bs[BK][BN];   // [k][n]

    const int t    = threadIdx.x;
    const int m0   = blockIdx.x * BM;
    const int lane = t & 31;
    const int row0 = (t >> 4) * 4;       // 0..60
    const int col0 = (t & 15) * 8;       // 0..120

    unsigned long long acc[4][4];
#pragma unroll
    for (int r = 0; r < 4; r++)
#pragma unroll
        for (int c = 0; c < 4; c++) acc[r][c] = 0ULL;

    for (int k0 = 0; k0 < DIN; k0 += BK) {
        // ---- A tile (64 rows x 32 k) transposed into As[k][m]. ----
        {
            int ar = t >> 2;          // 0..63
            int ak = (t & 3) * 8;     // 0,8,16,24
            float v[8];
            if (m0 + ar < M) {
                const float* src = A + (size_t)(m0 + ar) * DIN + k0 + ak;
                *(float4*)(v)     = *(const float4*)(src);
                *(float4*)(v + 4) = *(const float4*)(src + 4);
            } else {
#pragma unroll
                for (int i = 0; i < 8; i++) v[i] = 0.0f;
            }
#pragma unroll
            for (int i = 0; i < 8; i++) As[ak + i][ar] = v[i];
        }
        // ---- B tile (32 k x 128 n). ----
        {
            int rb = t >> 5;  // 0..7
#pragma unroll
            for (int i = 0; i < 4; i++) {
                int r = rb + i * 8;
                *(float4*)&Bs[r][lane * 4] =
                    *(const float4*)(W + (size_t)(k0 + r) * BN + lane * 4);
            }
        }
        __syncthreads();

#pragma unroll
        for (int k = 0; k < BK; k++) {
            float4 a4 = *(const float4*)&As[k][row0];
            unsigned long long b[4];
            *(ulonglong2*)(b)     = *(const ulonglong2*)&Bs[k][col0];
            *(ulonglong2*)(b + 2) = *(const ulonglong2*)&Bs[k][col0 + 4];
            float av[4] = {a4.x, a4.y, a4.z, a4.w};
#pragma unroll
            for (int r = 0; r < 4; r++) {
                unsigned long long ap;
                asm("mov.b64 %0, {%1, %1};" : "=l"(ap) : "f"(av[r]));
#pragma unroll
                for (int c = 0; c < 4; c++)
                    asm("fma.rn.f32x2 %0, %1, %2, %0;"
                        : "+l"(acc[r][c]) : "l"(ap), "l"(b[c]));
            }
        }
        __syncthreads();
    }

    // ---- Epilogue: unpack, add (scaled) bias, store. ----
    float bv[8];
    *(float4*)(bv)     = *(const float4*)(bias + col0);
    *(float4*)(bv + 4) = *(const float4*)(bias + col0 + 4);
#pragma unroll
    for (int r = 0; r < 4; r++) {
        int m = m0 + row0 + r;
        if (m < M) {
            float o[8];
#pragma unroll
            for (int c = 0; c < 4; c++)
                asm("mov.b64 {%0, %1}, %2;"
                    : "=f"(o[2 * c]), "=f"(o[2 * c + 1]) : "l"(acc[r][c]));
            float bs = SCALED_BIAS ? sumw[m] : 1.0f;
#pragma unroll
            for (int j = 0; j < 8; j++) o[j] += bs * bv[j];
            float* dst = C + (size_t)m * BN + col0;
            *(float4*)(dst)     = *(float4*)(o);
            *(float4*)(dst + 4) = *(float4*)(o + 4);
        }
    }
}

// ---------------------------------------------------------------------------
// Edge scatter (projected, 128-wide): one warp per edge, lane = one float4.
// red.global.add.v4.f32 -> 4x fewer atomic instructions than scalar atomicAdd.
// ---------------------------------------------------------------------------
__global__ __launch_bounds__(256)
void scatter_rel(const int* __restrict__ src, const int* __restrict__ dst,
                 const float* __restrict__ w, int rel, int E) {
    int gw   = (int)(((size_t)blockIdx.x * blockDim.x + threadIdx.x) >> 5);
    int lane = threadIdx.x & 31;
    if (gw >= E) return;

    int   sN = src[gw];
    int   dN = dst[gw];
    float ew = w[gw];

    const float* Wh = wh_ptr(rel);
    float*       S  = s_ptr(rel);

    float4 v = *(const float4*)(Wh + (size_t)sN * DO + lane * 4);
    v.x *= ew; v.y *= ew; v.z *= ew; v.w *= ew;

    float* p = S + (size_t)dN * DO + lane * 4;
    asm volatile("red.global.add.v4.f32 [%0], {%1, %2, %3, %4};"
                 :: "l"(p), "f"(v.x), "f"(v.y), "f"(v.z), "f"(v.w)
                 : "memory");

    if (lane == 0) atomicAdd(g_deg + deg_off(rel) + dN, 1.0f);
}

// ---------------------------------------------------------------------------
// wt aggregate-first scatter: raw 256-wide word features into the topic
// accumulator (2 MB, L2-hot). Warp per edge, lane = 8 floats (2 float4).
// No GEMM dependency -> runs concurrently with all projections.
// ---------------------------------------------------------------------------
__global__ __launch_bounds__(256)
void scatter_wt_raw(const float* __restrict__ feat,
                    const int* __restrict__ src, const int* __restrict__ dst,
                    const float* __restrict__ w, int E) {
    int gw   = (int)(((size_t)blockIdx.x * blockDim.x + threadIdx.x) >> 5);
    int lane = threadIdx.x & 31;
    if (gw >= E) return;

    int   sN = src[gw];
    int   dN = dst[gw];
    float ew = w[gw];

    const float* f = feat + (size_t)sN * DW + lane * 8;
    float4 v0 = *(const float4*)(f);
    float4 v1 = *(const float4*)(f + 4);
    v0.x *= ew; v0.y *= ew; v0.z *= ew; v0.w *= ew;
    v1.x *= ew; v1.y *= ew; v1.z *= ew; v1.w *= ew;

    float* p = g_agg_wt + (size_t)dN * DW + lane * 8;
    asm volatile("red.global.add.v4.f32 [%0], {%1, %2, %3, %4};"
                 :: "l"(p), "f"(v0.x), "f"(v0.y), "f"(v0.z), "f"(v0.w)
                 : "memory");
    asm volatile("red.global.add.v4.f32 [%0], {%1, %2, %3, %4};"
                 :: "l"(p + 4), "f"(v1.x), "f"(v1.y), "f"(v1.z), "f"(v1.w)
                 : "memory");

    if (lane == 0) atomicAdd(g_deg + DEG_WT + dN, 1.0f);
    if (lane == 1) atomicAdd(g_sumw_wt + dN, ew);
}

// ---------------------------------------------------------------------------
// Combine: per-destination mean, cross-etype sum, write output
// [h_word(50000x128) | h_topic(2000x128) | h_doc(50000x128)].
// ---------------------------------------------------------------------------
__device__ __forceinline__ float inv_or_zero(float d) {
    return d > 0.0f ? 1.0f / d : 0.0f;
}

__global__ __launch_bounds__(256)
void combine(float* __restrict__ out) {
    constexpr int ROWS = NW + NT + ND;          // 102000
    constexpr int TOT4 = ROWS * (DO / 4);       // float4 elements
    int i = (int)((size_t)blockIdx.x * blockDim.x + threadIdx.x);
    if (i >= TOT4) return;

    int row = i >> 5;           // DO/4 = 32 float4 per row
    int c   = (i & 31) * 4;     // float offset within row

    float4 o;
    if (row < NW) {
        float  inv = inv_or_zero(g_deg[DEG_WW + row]);
        float4 v   = *(const float4*)(g_s_ww + (size_t)row * DO + c);
        o = make_float4(v.x * inv, v.y * inv, v.z * inv, v.w * inv);
    } else if (row < NW + NT) {
        int    r    = row - NW;
        float  inv1 = inv_or_zero(g_deg[DEG_WT + r]);
        float  inv2 = inv_or_zero(g_deg[DEG_TT + r]);
        float4 v1   = *(const float4*)(g_s_wt + (size_t)r * DO + c);
        float4 v2   = *(const float4*)(g_s_tt + (size_t)r * DO + c);
        o = make_float4(v1.x * inv1 + v2.x * inv2, v1.y * inv1 + v2.y * inv2,
                        v1.z * inv1 + v2.z * inv2, v1.w * inv1 + v2.w * inv2);
    } else {
        int    r    = row - NW - NT;
        float  inv1 = inv_or_zero(g_deg[DEG_WD + r]);
        float  inv2 = inv_or_zero(g_deg[DEG_TD + r]);
        float4 v1   = *(const float4*)(g_s_wd + (size_t)r * DO + c);
        float4 v2   = *(const float4*)(g_s_td + (size_t)r * DO + c);
        o = make_float4(v1.x * inv1 + v2.x * inv2, v1.y * inv1 + v2.y * inv2,
                        v1.z * inv1 + v2.z * inv2, v1.w * inv1 + v2.w * inv2);
    }
    *(float4*)(out + (size_t)i * 4) = o;
}

// ---------------------------------------------------------------------------
// Host entry.
// Input order (metadata): 0 feat_word, 1 feat_topic,
//   2-4 ww(src,dst,w), 5-7 wt, 8-10 wd, 11-13 td, 14-16 tt,
//   17/18 W_ww/b_ww, 19/20 W_wt/b_wt, 21/22 W_wd/b_wd, 23/24 W_td/b_td,
//   25/26 W_tt/b_tt
//
// DAG (two streams + legacy):
//   legacy: zero -> G_ww -> G_wd -> G_tt -> G_td -> scat_wd -> scat_td
//                                                     -> [wait evS2] combine
//   s2:     [evZ] scat_wt_raw -> [evG_ww] scat_ww -> [evG_tt] scat_tt
//                              -> gemm_wt_small -> evS2
// wt uses aggregate-first (mean-agg is linear in Wh), eliminating one full
// 50000x256x128 projection from the GEMM chain.
// ---------------------------------------------------------------------------
extern "C" void kernel_launch(void* const* d_in, const int* in_sizes, int n_in,
                              void* d_out, int out_size) {
    static cudaStream_t s2 = nullptr;
    static cudaEvent_t  evZ, evGww, evGtt, evS2;
    if (s2 == nullptr) {
        cudaStreamCreateWithFlags(&s2, cudaStreamNonBlocking);
        cudaEventCreateWithFlags(&evZ,   cudaEventDisableTiming);
        cudaEventCreateWithFlags(&evGww, cudaEventDisableTiming);
        cudaEventCreateWithFlags(&evGtt, cudaEventDisableTiming);
        cudaEventCreateWithFlags(&evS2,  cudaEventDisableTiming);
    }

    const float* feat_word  = (const float*)d_in[0];
    const float* feat_topic = (const float*)d_in[1];

    const int*   ww_src = (const int*)d_in[2];
    const int*   ww_dst = (const int*)d_in[3];
    const float* ww_w   = (const float*)d_in[4];
    const int    E_ww   = in_sizes[2];

    const int*   wt_src = (const int*)d_in[5];
    const int*   wt_dst = (const int*)d_in[6];
    const float* wt_w   = (const float*)d_in[7];
    const int    E_wt   = in_sizes[5];

    const int*   wd_src = (const int*)d_in[8];
    const int*   wd_dst = (const int*)d_in[9];
    const float* wd_w   = (const float*)d_in[10];
    const int    E_wd   = in_sizes[8];

    const int*   td_src = (const int*)d_in[11];
    const int*   td_dst = (const int*)d_in[12];
    const float* td_w   = (const float*)d_in[13];
    const int    E_td   = in_sizes[11];

    const int*   tt_src = (const int*)d_in[14];
    const int*   tt_dst = (const int*)d_in[15];
    const float* tt_w   = (const float*)d_in[16];
    const int    E_tt   = in_sizes[14];

    const float* W_ww = (const float*)d_in[17]; const float* b_ww = (const float*)d_in[18];
    const float* W_wt = (const float*)d_in[19]; const float* b_wt = (const float*)d_in[20];
    const float* W_wd = (const float*)d_in[21]; const float* b_wd = (const float*)d_in[22];
    const float* W_td = (const float*)d_in[23]; const float* b_td = (const float*)d_in[24];
    const float* W_tt = (const float*)d_in[25]; const float* b_tt = (const float*)d_in[26];

    float* out = (float*)d_out;

    float* p_Wh_ww; cudaGetSymbolAddress((void**)&p_Wh_ww, g_Wh_ww);
    float* p_Wh_wd; cudaGetSymbolAddress((void**)&p_Wh_wd, g_Wh_wd);
    float* p_Wh_td; cudaGetSymbolAddress((void**)&p_Wh_td, g_Wh_td);
    float* p_Wh_tt; cudaGetSymbolAddress((void**)&p_Wh_tt, g_Wh_tt);
    float* p_s_wt;  cudaGetSymbolAddress((void**)&p_s_wt,  g_s_wt);
    float* p_agg;   cudaGetSymbolAddress((void**)&p_agg,   g_agg_wt);
    float* p_sumw;  cudaGetSymbolAddress((void**)&p_sumw,  g_sumw_wt);

    // 1. Zero accumulators + degrees (legacy stream).
    {
        const size_t maxe = (size_t)NW * DO;  // largest array span (6.4M)
        int blocks = (int)((maxe + 255) / 256);
        zero_all<<<blocks, 256>>>();
        cudaEventRecord(evZ, 0);
    }

    // 2. Projections (legacy stream). BM=64 -> 782 blocks for word GEMMs.
    {
        int gw = (NW + 63) / 64;
        gemm_bias_x2<DW, false><<<gw, 256>>>(feat_word, W_ww, b_ww, nullptr,
                                             p_Wh_ww, NW);
        cudaEventRecord(evGww, 0);
        gemm_bias_x2<DW, false><<<gw, 256>>>(feat_word, W_wd, b_wd, nullptr,
                                             p_Wh_wd, NW);
        int gt = (NT + 63) / 64;
        gemm_bias_x2<128, false><<<gt, 256>>>(feat_topic, W_tt, b_tt, nullptr,
                                              p_Wh_tt, NT);
        cudaEventRecord(evGtt, 0);
        gemm_bias_x2<128, false><<<gt, 256>>>(feat_topic, W_td, b_td, nullptr,
                                              p_Wh_td, NT);
    }

    // 3a. Side stream: wt raw scatter (only needs zero), then ww + tt
    //     scatters as their GEMMs complete, then the tiny wt projection.
    {
        cudaStreamWaitEvent(s2, evZ, 0);
        scatter_wt_raw<<<(E_wt + 7) / 8, 256, 0, s2>>>(feat_word, wt_src,
                                                       wt_dst, wt_w, E_wt);
        cudaStreamWaitEvent(s2, evGww, 0);
        scatter_rel<<<(E_ww + 7) / 8, 256, 0, s2>>>(ww_src, ww_dst, ww_w, 0, E_ww);
        cudaStreamWaitEvent(s2, evGtt, 0);
        scatter_rel<<<(E_tt + 7) / 8, 256, 0, s2>>>(tt_src, tt_dst, tt_w, 2, E_tt);
        // s_wt = agg_wt @ W_wt + sumw * b_wt   (2000 x 256 x 128, ~5us)
        gemm_bias_x2<DW, true><<<(NT + 63) / 64, 256, 0, s2>>>(
            p_agg, W_wt, b_wt, p_sumw, p_s_wt, NT);
        cudaEventRecord(evS2, s2);
    }

    // 3b. Legacy stream: wd + td scatters (their GEMMs are earlier in-stream).
    {
        scatter_rel<<<(E_wd + 7) / 8, 256>>>(wd_src, wd_dst, wd_w, 3, E_wd);
        scatter_rel<<<(E_td + 7) / 8, 256>>>(td_src, td_dst, td_w, 4, E_td);
    }

    // 4. Join and combine.
    {
        cudaStreamWaitEvent(0, evS2, 0);
        constexpr int TOT4 = (NW + NT + ND) * (DO / 4);
        combine<<<(TOT4 + 255) / 256, 256>>>(out);
    }
}